// round 10
// baseline (speedup 1.0000x reference)
#include <cuda_runtime.h>
#include <cuda_bf16.h>
#include <math.h>
#include <stdint.h>

// Problem constants
#define N_NODES 50000
#define N_EDGES 800000
#define IN_CH   128
#define HID     256
#define OUT_CH  40

// -------- static device scratch (allocation-free) --------
__device__ float g_buf0[(size_t)N_NODES * HID];
__device__ float g_buf1[(size_t)N_NODES * HID];
__device__ float g_buf2[(size_t)N_NODES * HID];

// tf32-rounded weights
__device__ float g_w1[IN_CH * HID];
__device__ float g_w2[HID * HID];
__device__ float g_w3[HID * OUT_CH];

// CSR-by-dst scratch (packed: .x = src, .y = float-bits of weight)
#define NSB ((N_NODES + 255) / 256)   // 196 scan blocks
__device__ int   g_deg[N_NODES];
__device__ int   g_off[N_NODES + 1];
__device__ int   g_pos[N_NODES];
__device__ int   g_bsum[NSB];
__device__ int   g_boff[NSB];
__device__ int2  g_csr[N_EDGES];

__device__ __forceinline__ float rnd_tf32(float f) {
    uint32_t r;
    asm("cvt.rna.tf32.f32 %0, %1;" : "=r"(r) : "f"(f));
    return __uint_as_float(r);
}

// =========================================================
// tf32 tensor-core GEMM: C[M,N] = A[M,K] @ B[K,N]
// A and B must be tf32-pre-rounded fp32.
// EPI: 0 = plain store, 1 = rnd_tf32(relu(acc + bias[n]))
// BN: block N-tile (128 or 64). Block 128xBNx32, 8 warps (4M x 2N),
// warp tile 32 x BN/2. A k-major + XOR swizzle (R4 proven layout),
// register-prefetch double buffering, no cvt in hot path.
// =========================================================
#define GBM 128
#define GBK 32
#define ASTRIDE 136

__device__ __forceinline__ void mma_tf32(float* d, const uint32_t* a, const uint32_t* b) {
    asm volatile(
        "mma.sync.aligned.m16n8k8.row.col.f32.tf32.tf32.f32 "
        "{%0,%1,%2,%3}, {%4,%5,%6,%7}, {%8,%9}, {%0,%1,%2,%3};\n"
        : "+f"(d[0]), "+f"(d[1]), "+f"(d[2]), "+f"(d[3])
        : "r"(a[0]), "r"(a[1]), "r"(a[2]), "r"(a[3]),
          "r"(b[0]), "r"(b[1]));
}

template <int EPI, int BN>
__global__ __launch_bounds__(256) void gemm_tf32(
    const float* __restrict__ A, const float* __restrict__ B,
    const float* __restrict__ bias, float* __restrict__ C,
    int M, int N, int K)
{
    constexpr int BSTR   = BN + 8;     // word stride, %32 == 8 (conflict-free phases)
    constexpr int NJ     = BN / 16;    // 8-col groups per warp (warp N-tile = BN/2)
    constexpr int NB4    = BN / 32;    // B float4 loads per thread
    constexpr int BLANES = BN / 4;     // float4 lanes per B row

    __shared__ __align__(16) float As[GBK * ASTRIDE];
    __shared__ __align__(16) float Bs[GBK * BSTR];

    const int tid  = threadIdx.x;
    const int warp = tid >> 5;
    const int lane = tid & 31;
    const int bm = blockIdx.y * GBM;
    const int bn = blockIdx.x * BN;

    const int wm = (warp >> 1) * 32;
    const int wn = (warp & 1) * (BN / 2);
    const int qr = lane >> 2;
    const int qc = lane & 3;

    const int ar  = tid >> 3;          // A base row (i*32 added)
    const int ac4 = (tid & 7) * 4;     // A k-offset

    float acc[2][NJ][4];
#pragma unroll
    for (int i = 0; i < 2; i++)
#pragma unroll
        for (int j = 0; j < NJ; j++)
#pragma unroll
            for (int t = 0; t < 4; t++) acc[i][j][t] = 0.f;

    float4 ra[4], rb[NB4];

    // ---- preload tile k0 = 0 ----
#pragma unroll
    for (int i = 0; i < 4; i++) {
        int gr = bm + ar + i * 32;
        ra[i] = (gr < M)
            ? *reinterpret_cast<const float4*>(A + (long)gr * K + ac4)
            : make_float4(0.f, 0.f, 0.f, 0.f);
    }
#pragma unroll
    for (int i = 0; i < NB4; i++) {
        int idx  = tid + i * 256;
        int krow = idx / BLANES;
        int bc4  = (idx % BLANES) * 4;
        int gc = bn + bc4;
        float4 v = make_float4(0.f, 0.f, 0.f, 0.f);
        if (gc + 3 < N) {
            v = *reinterpret_cast<const float4*>(B + (long)krow * N + gc);
        } else {
            float* pv = &v.x;
#pragma unroll
            for (int j = 0; j < 4; j++)
                if (gc + j < N) pv[j] = B[(long)krow * N + gc + j];
        }
        rb[i] = v;
    }

    for (int k0 = 0; k0 < K; k0 += GBK) {
        // ---- store regs -> smem ----
#pragma unroll
        for (int i = 0; i < 4; i++) {
            int row = ar + i * 32;
            int sm = row ^ (((ac4 >> 2) & 7) << 3);
            const float* pv = &ra[i].x;
#pragma unroll
            for (int j = 0; j < 4; j++)
                As[(ac4 + j) * ASTRIDE + sm] = pv[j];
        }
#pragma unroll
        for (int i = 0; i < NB4; i++) {
            int idx  = tid + i * 256;
            int krow = idx / BLANES;
            int bc4  = (idx % BLANES) * 4;
            *reinterpret_cast<float4*>(&Bs[krow * BSTR + bc4]) = rb[i];
        }
        __syncthreads();

        // ---- prefetch next tile while mma runs ----
        if (k0 + GBK < K) {
            int kn = k0 + GBK;
#pragma unroll
            for (int i = 0; i < 4; i++) {
                int gr = bm + ar + i * 32;
                ra[i] = (gr < M)
                    ? *reinterpret_cast<const float4*>(A + (long)gr * K + kn + ac4)
                    : make_float4(0.f, 0.f, 0.f, 0.f);
            }
#pragma unroll
            for (int i = 0; i < NB4; i++) {
                int idx  = tid + i * 256;
                int krow = idx / BLANES;
                int bc4  = (idx % BLANES) * 4;
                int gc = bn + bc4;
                float4 v = make_float4(0.f, 0.f, 0.f, 0.f);
                if (gc + 3 < N) {
                    v = *reinterpret_cast<const float4*>(B + (long)(kn + krow) * N + gc);
                } else {
                    float* pv = &v.x;
#pragma unroll
                    for (int j = 0; j < 4; j++)
                        if (gc + j < N) pv[j] = B[(long)(kn + krow) * N + gc + j];
                }
                rb[i] = v;
            }
        }

        // ---- 4 k8-steps ----
#pragma unroll
        for (int ks = 0; ks < 4; ks++) {
            int kb = ks * 8;
            int kA0 = kb + qc;
            int kA1 = kb + qc + 4;
            int sw0 = ((kA0 >> 2) & 7) << 3;
            int sw1 = ((kA1 >> 2) & 7) << 3;

            uint32_t a[2][4];
#pragma unroll
            for (int i = 0; i < 2; i++) {
                int mb = wm + i * 16;
                a[i][0] = __float_as_uint(As[kA0 * ASTRIDE + ((mb + qr)     ^ sw0)]);
                a[i][1] = __float_as_uint(As[kA0 * ASTRIDE + ((mb + qr + 8) ^ sw0)]);
                a[i][2] = __float_as_uint(As[kA1 * ASTRIDE + ((mb + qr)     ^ sw1)]);
                a[i][3] = __float_as_uint(As[kA1 * ASTRIDE + ((mb + qr + 8) ^ sw1)]);
            }
            uint32_t b[NJ][2];
#pragma unroll
            for (int j = 0; j < NJ; j++) {
                int nb = wn + j * 8;
                b[j][0] = __float_as_uint(Bs[(kb + qc)     * BSTR + nb + qr]);
                b[j][1] = __float_as_uint(Bs[(kb + qc + 4) * BSTR + nb + qr]);
            }
#pragma unroll
            for (int i = 0; i < 2; i++)
#pragma unroll
                for (int j = 0; j < NJ; j++)
                    mma_tf32(acc[i][j], a[i], b[j]);
        }
        __syncthreads();
    }

    // ---- epilogue ----
#pragma unroll
    for (int i = 0; i < 2; i++) {
        int r0 = bm + wm + i * 16 + qr;
        int r1 = r0 + 8;
#pragma unroll
        for (int j = 0; j < NJ; j++) {
            int c0 = bn + wn + j * 8 + qc * 2;
            float v0 = acc[i][j][0], v1 = acc[i][j][1];
            float v2 = acc[i][j][2], v3 = acc[i][j][3];
            if (EPI == 1) {
                float bb0 = (c0 < N) ? bias[c0] : 0.f;
                float bb1 = (c0 + 1 < N) ? bias[c0 + 1] : 0.f;
                v0 = rnd_tf32(fmaxf(v0 + bb0, 0.f));
                v1 = rnd_tf32(fmaxf(v1 + bb1, 0.f));
                v2 = rnd_tf32(fmaxf(v2 + bb0, 0.f));
                v3 = rnd_tf32(fmaxf(v3 + bb1, 0.f));
            }
            if (r0 < M) {
                if (c0     < N) C[(long)r0 * N + c0]     = v0;
                if (c0 + 1 < N) C[(long)r0 * N + c0 + 1] = v1;
            }
            if (r1 < M) {
                if (c0     < N) C[(long)r1 * N + c0]     = v2;
                if (c0 + 1 < N) C[(long)r1 * N + c0 + 1] = v3;
            }
        }
    }
}

// =========================================================
// weight prep: round to tf32
// =========================================================
__global__ void prep_kernel(const float* __restrict__ W1,
                            const float* __restrict__ W2,
                            const float* __restrict__ W3)
{
    int i = blockIdx.x * blockDim.x + threadIdx.x;
    if (i < IN_CH * HID)  g_w1[i] = rnd_tf32(W1[i]);
    if (i < HID * HID)    g_w2[i] = rnd_tf32(W2[i]);
    if (i < HID * OUT_CH) g_w3[i] = rnd_tf32(W3[i]);
}

// =========================================================
// CSR build: hist -> 3-stage parallel scan -> fill
// =========================================================
__global__ void zero_deg_kernel()
{
    int i = blockIdx.x * blockDim.x + threadIdx.x;
    if (i < N_NODES) g_deg[i] = 0;
}

__global__ void hist_kernel(const int* __restrict__ dst)
{
    int e = blockIdx.x * blockDim.x + threadIdx.x;
    if (e < N_EDGES) atomicAdd(&g_deg[dst[e]], 1);
}

__global__ __launch_bounds__(256) void scan_block_kernel()
{
    __shared__ int s[256];
    int t = threadIdx.x;
    int i = blockIdx.x * 256 + t;
    int v = (i < N_NODES) ? g_deg[i] : 0;
    s[t] = v;
    __syncthreads();
#pragma unroll
    for (int o = 1; o < 256; o <<= 1) {
        int add = (t >= o) ? s[t - o] : 0;
        __syncthreads();
        s[t] += add;
        __syncthreads();
    }
    if (i < N_NODES) g_off[i] = s[t] - v;
    if (t == 255) g_bsum[blockIdx.x] = s[255];
}

__global__ __launch_bounds__(256) void scan_top_kernel()
{
    __shared__ int s[256];
    int t = threadIdx.x;
    int v = (t < NSB) ? g_bsum[t] : 0;
    s[t] = v;
    __syncthreads();
#pragma unroll
    for (int o = 1; o < 256; o <<= 1) {
        int add = (t >= o) ? s[t - o] : 0;
        __syncthreads();
        s[t] += add;
        __syncthreads();
    }
    if (t < NSB) g_boff[t] = s[t] - v;
}

__global__ void scan_finalize_kernel()
{
    int i = blockIdx.x * blockDim.x + threadIdx.x;
    if (i < N_NODES) {
        int o = g_off[i] + g_boff[i >> 8];
        g_off[i] = o;
        g_pos[i] = o;
    }
    if (i == 0) g_off[N_NODES] = N_EDGES;
}

__global__ void fill_kernel(const int* __restrict__ src,
                            const int* __restrict__ dst,
                            const float* __restrict__ ew)
{
    int e = blockIdx.x * blockDim.x + threadIdx.x;
    if (e >= N_EDGES) return;
    int p = atomicAdd(&g_pos[dst[e]], 1);
    g_csr[p] = make_int2(src[e], __float_as_int(ew[e]));
}

// =========================================================
// CSR gather: agg[n] = sum_{e} w_e * h[src_e]
// EPI: 0 = rnd_tf32(acc), 1 = rnd_tf32(relu(acc + bias[ch]))
// =========================================================
template <int C4, int EPI>
__global__ __launch_bounds__(256) void gather_kernel(
    const float* __restrict__ h, const float* __restrict__ bias,
    float* __restrict__ agg)
{
    const int SLICES = C4 / 32;
    int gw = (int)(((long)blockIdx.x * blockDim.x + threadIdx.x) >> 5);
    int lane = threadIdx.x & 31;
    int n = gw / SLICES;
    int sl = gw - n * SLICES;
    if (n >= N_NODES) return;
    int c = sl * 32 + lane;

    const float4* hp = reinterpret_cast<const float4*>(h);
    int e   = g_off[n];
    int end = g_off[n + 1];

    float4 acc = make_float4(0.f, 0.f, 0.f, 0.f);
    for (; e + 1 < end; e += 2) {
        int2 t0 = g_csr[e];
        int2 t1 = g_csr[e + 1];
        float w0 = __int_as_float(t0.y);
        float w1 = __int_as_float(t1.y);
        float4 v0 = hp[(long)t0.x * C4 + c];
        float4 v1 = hp[(long)t1.x * C4 + c];
        acc.x += w0 * v0.x + w1 * v1.x;
        acc.y += w0 * v0.y + w1 * v1.y;
        acc.z += w0 * v0.z + w1 * v1.z;
        acc.w += w0 * v0.w + w1 * v1.w;
    }
    if (e < end) {
        int2 t0 = g_csr[e];
        float w0 = __int_as_float(t0.y);
        float4 v0 = hp[(long)t0.x * C4 + c];
        acc.x += w0 * v0.x;
        acc.y += w0 * v0.y;
        acc.z += w0 * v0.z;
        acc.w += w0 * v0.w;
    }

    if (EPI == 1) {
        float4 bb = *reinterpret_cast<const float4*>(bias + c * 4);
        acc.x = fmaxf(acc.x + bb.x, 0.f);
        acc.y = fmaxf(acc.y + bb.y, 0.f);
        acc.z = fmaxf(acc.z + bb.z, 0.f);
        acc.w = fmaxf(acc.w + bb.w, 0.f);
    }
    acc.x = rnd_tf32(acc.x);
    acc.y = rnd_tf32(acc.y);
    acc.z = rnd_tf32(acc.z);
    acc.w = rnd_tf32(acc.w);

    reinterpret_cast<float4*>(agg)[(long)n * C4 + c] = acc;
}

// =========================================================
// Fused layer-3 aggregation + bias + log_softmax.
// One warp per node: lane holds ch=lane, and ch=32+lane for lane<8.
// out[n] = log_softmax(sum_e w_e * h[src_e] + b)
// =========================================================
__global__ __launch_bounds__(256) void gather40_lsm_kernel(
    const float* __restrict__ h, const float* __restrict__ b,
    float* __restrict__ out)
{
    int n = (int)(((long)blockIdx.x * blockDim.x + threadIdx.x) >> 5);
    int lane = threadIdx.x & 31;
    if (n >= N_NODES) return;

    int e   = g_off[n];
    int end = g_off[n + 1];
    float acc0 = 0.f, acc1 = 0.f;

    for (; e + 1 < end; e += 2) {
        int2 t0 = g_csr[e];
        int2 t1 = g_csr[e + 1];
        float w0 = __int_as_float(t0.y);
        float w1 = __int_as_float(t1.y);
        const float* r0 = h + (long)t0.x * OUT_CH;
        const float* r1 = h + (long)t1.x * OUT_CH;
        acc0 += w0 * r0[lane] + w1 * r1[lane];
        if (lane < 8) acc1 += w0 * r0[32 + lane] + w1 * r1[32 + lane];
    }
    if (e < end) {
        int2 t0 = g_csr[e];
        float w0 = __int_as_float(t0.y);
        const float* r0 = h + (long)t0.x * OUT_CH;
        acc0 += w0 * r0[lane];
        if (lane < 8) acc1 += w0 * r0[32 + lane];
    }

    float v0 = acc0 + b[lane];
    float v1 = (lane < 8) ? (acc1 + b[32 + lane]) : -INFINITY;

    float m = fmaxf(v0, v1);
#pragma unroll
    for (int o = 16; o > 0; o >>= 1)
        m = fmaxf(m, __shfl_xor_sync(0xFFFFFFFFu, m, o));

    float s = __expf(v0 - m) + ((lane < 8) ? __expf(v1 - m) : 0.f);
#pragma unroll
    for (int o = 16; o > 0; o >>= 1)
        s += __shfl_xor_sync(0xFFFFFFFFu, s, o);

    float lse = m + logf(s);
    float* row = out + (long)n * OUT_CH;
    row[lane] = v0 - lse;
    if (lane < 8) row[32 + lane] = v1 - lse;
}

// ---------------------------------------------------------
// launch
// ---------------------------------------------------------
extern "C" void kernel_launch(void* const* d_in, const int* in_sizes, int n_in,
                              void* d_out, int out_size)
{
    const float* x  = (const float*)d_in[0];
    const int*   ei = (const int*)d_in[1];
    const float* ew = (const float*)d_in[2];
    const float* W1 = (const float*)d_in[3];
    const float* b1 = (const float*)d_in[4];
    const float* W2 = (const float*)d_in[5];
    const float* b2 = (const float*)d_in[6];
    const float* W3 = (const float*)d_in[7];
    const float* b3 = (const float*)d_in[8];
    float* out = (float*)d_out;

    const int* src = ei;
    const int* dst = ei + N_EDGES;

    float *buf0, *buf1, *buf2, *w1p, *w2p, *w3p;
    cudaGetSymbolAddress((void**)&buf0, g_buf0);
    cudaGetSymbolAddress((void**)&buf1, g_buf1);
    cudaGetSymbolAddress((void**)&buf2, g_buf2);
    cudaGetSymbolAddress((void**)&w1p, g_w1);
    cudaGetSymbolAddress((void**)&w2p, g_w2);
    cudaGetSymbolAddress((void**)&w3p, g_w3);

    const int mtiles = (N_NODES + GBM - 1) / GBM;   // 391
    dim3 grid_wide(HID / 128, mtiles);              // 2 x 391 (BN=128)
    dim3 grid_narrow(1, mtiles);                    // 1 x 391 (BN=64, N=40)

    // weight prep + CSR build (parallel scan)
    prep_kernel<<<(HID * HID + 255) / 256, 256>>>(W1, W2, W3);
    zero_deg_kernel<<<(N_NODES + 255) / 256, 256>>>();
    hist_kernel<<<(N_EDGES + 255) / 256, 256>>>(dst);
    scan_block_kernel<<<NSB, 256>>>();
    scan_top_kernel<<<1, 256>>>();
    scan_finalize_kernel<<<NSB, 256>>>();
    fill_kernel<<<(N_EDGES + 255) / 256, 256>>>(src, dst, ew);

    // ---- layer 1 (reordered): agg_x = A_hat @ x ; h1 = relu(agg_x @ W1 + b1) ----
    gather_kernel<32, 0><<<(N_NODES * 32 + 255) / 256, 256>>>(x, nullptr, buf1);
    gemm_tf32<1, 128><<<grid_wide, 256>>>(buf1, w1p, b1, buf0, N_NODES, HID, IN_CH);

    // ---- layer 2: h2 = h1r @ W2 ; agg2 = relu(A_hat @ h2 + b2) ----
    gemm_tf32<0, 128><<<grid_wide, 256>>>(buf0, w2p, nullptr, buf2, N_NODES, HID, HID);
    gather_kernel<64, 1><<<(N_NODES * 2 * 32 + 255) / 256, 256>>>(buf2, b2, buf1);

    // ---- layer 3: h3 = agg2r @ W3 ; out = log_softmax(A_hat @ h3 + b3) ----
    gemm_tf32<0, 64><<<grid_narrow, 256>>>(buf1, w3p, nullptr, buf0, N_NODES, OUT_CH, HID);
    gather40_lsm_kernel<<<(N_NODES * 32 + 255) / 256, 256>>>(buf0, b3, out);
}

// round 11
// speedup vs baseline: 1.0062x; 1.0062x over previous
#include <cuda_runtime.h>
#include <cuda_bf16.h>
#include <math.h>
#include <stdint.h>

// Problem constants
#define N_NODES 50000
#define N_EDGES 800000
#define IN_CH   128
#define HID     256
#define OUT_CH  40

// -------- static device scratch (allocation-free) --------
__device__ float g_buf0[(size_t)N_NODES * HID];
__device__ float g_buf1[(size_t)N_NODES * HID];
__device__ float g_buf2[(size_t)N_NODES * HID];

// tf32-rounded weights
__device__ float g_w1[IN_CH * HID];
__device__ float g_w2[HID * HID];
__device__ float g_w3[HID * OUT_CH];

// CSR-by-dst scratch (packed: .x = src, .y = float-bits of weight)
#define NSB ((N_NODES + 255) / 256)   // 196 scan blocks
__device__ int   g_deg[N_NODES];
__device__ int   g_off[N_NODES + 1];
__device__ int   g_pos[N_NODES];
__device__ int   g_bsum[NSB];
__device__ int   g_boff[NSB];
__device__ int2  g_csr[N_EDGES];

__device__ __forceinline__ float rnd_tf32(float f) {
    uint32_t r;
    asm("cvt.rna.tf32.f32 %0, %1;" : "=r"(r) : "f"(f));
    return __uint_as_float(r);
}

// =========================================================
// tf32 tensor-core GEMM: C[M,N] = A[M,K] @ B[K,N]
// A and B must be tf32-pre-rounded fp32.
// EPI: 0 = plain store, 1 = rnd_tf32(relu(acc + bias[n]))
// BN: block N-tile (128 or 64). Block 128xBNx32, 8 warps (4M x 2N),
// warp tile 32 x BN/2. A k-major + XOR swizzle (R4 proven layout),
// register-prefetch double buffering, no cvt in hot path.
// =========================================================
#define GBM 128
#define GBK 32
#define ASTRIDE 136

__device__ __forceinline__ void mma_tf32(float* d, const uint32_t* a, const uint32_t* b) {
    asm volatile(
        "mma.sync.aligned.m16n8k8.row.col.f32.tf32.tf32.f32 "
        "{%0,%1,%2,%3}, {%4,%5,%6,%7}, {%8,%9}, {%0,%1,%2,%3};\n"
        : "+f"(d[0]), "+f"(d[1]), "+f"(d[2]), "+f"(d[3])
        : "r"(a[0]), "r"(a[1]), "r"(a[2]), "r"(a[3]),
          "r"(b[0]), "r"(b[1]));
}

template <int EPI, int BN>
__global__ __launch_bounds__(256) void gemm_tf32(
    const float* __restrict__ A, const float* __restrict__ B,
    const float* __restrict__ bias, float* __restrict__ C,
    int M, int N, int K)
{
    constexpr int BSTR   = BN + 8;     // word stride, %32 == 8 (conflict-free phases)
    constexpr int NJ     = BN / 16;    // 8-col groups per warp (warp N-tile = BN/2)
    constexpr int NB4    = BN / 32;    // B float4 loads per thread
    constexpr int BLANES = BN / 4;     // float4 lanes per B row

    __shared__ __align__(16) float As[GBK * ASTRIDE];
    __shared__ __align__(16) float Bs[GBK * BSTR];

    const int tid  = threadIdx.x;
    const int warp = tid >> 5;
    const int lane = tid & 31;
    const int bm = blockIdx.y * GBM;
    const int bn = blockIdx.x * BN;

    const int wm = (warp >> 1) * 32;
    const int wn = (warp & 1) * (BN / 2);
    const int qr = lane >> 2;
    const int qc = lane & 3;

    const int ar  = tid >> 3;          // A base row (i*32 added)
    const int ac4 = (tid & 7) * 4;     // A k-offset

    float acc[2][NJ][4];
#pragma unroll
    for (int i = 0; i < 2; i++)
#pragma unroll
        for (int j = 0; j < NJ; j++)
#pragma unroll
            for (int t = 0; t < 4; t++) acc[i][j][t] = 0.f;

    float4 ra[4], rb[NB4];

    // ---- preload tile k0 = 0 ----
#pragma unroll
    for (int i = 0; i < 4; i++) {
        int gr = bm + ar + i * 32;
        ra[i] = (gr < M)
            ? *reinterpret_cast<const float4*>(A + (long)gr * K + ac4)
            : make_float4(0.f, 0.f, 0.f, 0.f);
    }
#pragma unroll
    for (int i = 0; i < NB4; i++) {
        int idx  = tid + i * 256;
        int krow = idx / BLANES;
        int bc4  = (idx % BLANES) * 4;
        int gc = bn + bc4;
        float4 v = make_float4(0.f, 0.f, 0.f, 0.f);
        if (gc + 3 < N) {
            v = *reinterpret_cast<const float4*>(B + (long)krow * N + gc);
        } else {
            float* pv = &v.x;
#pragma unroll
            for (int j = 0; j < 4; j++)
                if (gc + j < N) pv[j] = B[(long)krow * N + gc + j];
        }
        rb[i] = v;
    }

    for (int k0 = 0; k0 < K; k0 += GBK) {
        // ---- store regs -> smem ----
#pragma unroll
        for (int i = 0; i < 4; i++) {
            int row = ar + i * 32;
            int sm = row ^ (((ac4 >> 2) & 7) << 3);
            const float* pv = &ra[i].x;
#pragma unroll
            for (int j = 0; j < 4; j++)
                As[(ac4 + j) * ASTRIDE + sm] = pv[j];
        }
#pragma unroll
        for (int i = 0; i < NB4; i++) {
            int idx  = tid + i * 256;
            int krow = idx / BLANES;
            int bc4  = (idx % BLANES) * 4;
            *reinterpret_cast<float4*>(&Bs[krow * BSTR + bc4]) = rb[i];
        }
        __syncthreads();

        // ---- prefetch next tile while mma runs ----
        if (k0 + GBK < K) {
            int kn = k0 + GBK;
#pragma unroll
            for (int i = 0; i < 4; i++) {
                int gr = bm + ar + i * 32;
                ra[i] = (gr < M)
                    ? *reinterpret_cast<const float4*>(A + (long)gr * K + kn + ac4)
                    : make_float4(0.f, 0.f, 0.f, 0.f);
            }
#pragma unroll
            for (int i = 0; i < NB4; i++) {
                int idx  = tid + i * 256;
                int krow = idx / BLANES;
                int bc4  = (idx % BLANES) * 4;
                int gc = bn + bc4;
                float4 v = make_float4(0.f, 0.f, 0.f, 0.f);
                if (gc + 3 < N) {
                    v = *reinterpret_cast<const float4*>(B + (long)(kn + krow) * N + gc);
                } else {
                    float* pv = &v.x;
#pragma unroll
                    for (int j = 0; j < 4; j++)
                        if (gc + j < N) pv[j] = B[(long)(kn + krow) * N + gc + j];
                }
                rb[i] = v;
            }
        }

        // ---- 4 k8-steps ----
#pragma unroll
        for (int ks = 0; ks < 4; ks++) {
            int kb = ks * 8;
            int kA0 = kb + qc;
            int kA1 = kb + qc + 4;
            int sw0 = ((kA0 >> 2) & 7) << 3;
            int sw1 = ((kA1 >> 2) & 7) << 3;

            uint32_t a[2][4];
#pragma unroll
            for (int i = 0; i < 2; i++) {
                int mb = wm + i * 16;
                a[i][0] = __float_as_uint(As[kA0 * ASTRIDE + ((mb + qr)     ^ sw0)]);
                a[i][1] = __float_as_uint(As[kA0 * ASTRIDE + ((mb + qr + 8) ^ sw0)]);
                a[i][2] = __float_as_uint(As[kA1 * ASTRIDE + ((mb + qr)     ^ sw1)]);
                a[i][3] = __float_as_uint(As[kA1 * ASTRIDE + ((mb + qr + 8) ^ sw1)]);
            }
            uint32_t b[NJ][2];
#pragma unroll
            for (int j = 0; j < NJ; j++) {
                int nb = wn + j * 8;
                b[j][0] = __float_as_uint(Bs[(kb + qc)     * BSTR + nb + qr]);
                b[j][1] = __float_as_uint(Bs[(kb + qc + 4) * BSTR + nb + qr]);
            }
#pragma unroll
            for (int i = 0; i < 2; i++)
#pragma unroll
                for (int j = 0; j < NJ; j++)
                    mma_tf32(acc[i][j], a[i], b[j]);
        }
        __syncthreads();
    }

    // ---- epilogue ----
#pragma unroll
    for (int i = 0; i < 2; i++) {
        int r0 = bm + wm + i * 16 + qr;
        int r1 = r0 + 8;
#pragma unroll
        for (int j = 0; j < NJ; j++) {
            int c0 = bn + wn + j * 8 + qc * 2;
            float v0 = acc[i][j][0], v1 = acc[i][j][1];
            float v2 = acc[i][j][2], v3 = acc[i][j][3];
            if (EPI == 1) {
                float bb0 = (c0 < N) ? bias[c0] : 0.f;
                float bb1 = (c0 + 1 < N) ? bias[c0 + 1] : 0.f;
                v0 = rnd_tf32(fmaxf(v0 + bb0, 0.f));
                v1 = rnd_tf32(fmaxf(v1 + bb1, 0.f));
                v2 = rnd_tf32(fmaxf(v2 + bb0, 0.f));
                v3 = rnd_tf32(fmaxf(v3 + bb1, 0.f));
            }
            if (r0 < M) {
                if (c0     < N) C[(long)r0 * N + c0]     = v0;
                if (c0 + 1 < N) C[(long)r0 * N + c0 + 1] = v1;
            }
            if (r1 < M) {
                if (c0     < N) C[(long)r1 * N + c0]     = v2;
                if (c0 + 1 < N) C[(long)r1 * N + c0 + 1] = v3;
            }
        }
    }
}

// =========================================================
// weight prep: round to tf32
// =========================================================
__global__ void prep_kernel(const float* __restrict__ W1,
                            const float* __restrict__ W2,
                            const float* __restrict__ W3)
{
    int i = blockIdx.x * blockDim.x + threadIdx.x;
    if (i < IN_CH * HID)  g_w1[i] = rnd_tf32(W1[i]);
    if (i < HID * HID)    g_w2[i] = rnd_tf32(W2[i]);
    if (i < HID * OUT_CH) g_w3[i] = rnd_tf32(W3[i]);
}

// =========================================================
// CSR build: hist -> 3-stage parallel scan -> fill
// =========================================================
__global__ void zero_deg_kernel()
{
    int i = blockIdx.x * blockDim.x + threadIdx.x;
    if (i < N_NODES) g_deg[i] = 0;
}

__global__ void hist_kernel(const int* __restrict__ dst)
{
    int e = blockIdx.x * blockDim.x + threadIdx.x;
    if (e < N_EDGES) atomicAdd(&g_deg[dst[e]], 1);
}

__global__ __launch_bounds__(256) void scan_block_kernel()
{
    __shared__ int s[256];
    int t = threadIdx.x;
    int i = blockIdx.x * 256 + t;
    int v = (i < N_NODES) ? g_deg[i] : 0;
    s[t] = v;
    __syncthreads();
#pragma unroll
    for (int o = 1; o < 256; o <<= 1) {
        int add = (t >= o) ? s[t - o] : 0;
        __syncthreads();
        s[t] += add;
        __syncthreads();
    }
    if (i < N_NODES) g_off[i] = s[t] - v;
    if (t == 255) g_bsum[blockIdx.x] = s[255];
}

__global__ __launch_bounds__(256) void scan_top_kernel()
{
    __shared__ int s[256];
    int t = threadIdx.x;
    int v = (t < NSB) ? g_bsum[t] : 0;
    s[t] = v;
    __syncthreads();
#pragma unroll
    for (int o = 1; o < 256; o <<= 1) {
        int add = (t >= o) ? s[t - o] : 0;
        __syncthreads();
        s[t] += add;
        __syncthreads();
    }
    if (t < NSB) g_boff[t] = s[t] - v;
}

__global__ void scan_finalize_kernel()
{
    int i = blockIdx.x * blockDim.x + threadIdx.x;
    if (i < N_NODES) {
        int o = g_off[i] + g_boff[i >> 8];
        g_off[i] = o;
        g_pos[i] = o;
    }
    if (i == 0) g_off[N_NODES] = N_EDGES;
}

__global__ void fill_kernel(const int* __restrict__ src,
                            const int* __restrict__ dst,
                            const float* __restrict__ ew)
{
    int e = blockIdx.x * blockDim.x + threadIdx.x;
    if (e >= N_EDGES) return;
    int p = atomicAdd(&g_pos[dst[e]], 1);
    g_csr[p] = make_int2(src[e], __float_as_int(ew[e]));
}

// =========================================================
// CSR gather: agg[n] = sum_{e} w_e * h[src_e]
// EPI: 0 = rnd_tf32(acc), 1 = rnd_tf32(relu(acc + bias[ch]))
// =========================================================
template <int C4, int EPI>
__global__ __launch_bounds__(256) void gather_kernel(
    const float* __restrict__ h, const float* __restrict__ bias,
    float* __restrict__ agg)
{
    const int SLICES = C4 / 32;
    int gw = (int)(((long)blockIdx.x * blockDim.x + threadIdx.x) >> 5);
    int lane = threadIdx.x & 31;
    int n = gw / SLICES;
    int sl = gw - n * SLICES;
    if (n >= N_NODES) return;
    int c = sl * 32 + lane;

    const float4* hp = reinterpret_cast<const float4*>(h);
    int e   = g_off[n];
    int end = g_off[n + 1];

    float4 acc = make_float4(0.f, 0.f, 0.f, 0.f);
    for (; e + 1 < end; e += 2) {
        int2 t0 = g_csr[e];
        int2 t1 = g_csr[e + 1];
        float w0 = __int_as_float(t0.y);
        float w1 = __int_as_float(t1.y);
        float4 v0 = hp[(long)t0.x * C4 + c];
        float4 v1 = hp[(long)t1.x * C4 + c];
        acc.x += w0 * v0.x + w1 * v1.x;
        acc.y += w0 * v0.y + w1 * v1.y;
        acc.z += w0 * v0.z + w1 * v1.z;
        acc.w += w0 * v0.w + w1 * v1.w;
    }
    if (e < end) {
        int2 t0 = g_csr[e];
        float w0 = __int_as_float(t0.y);
        float4 v0 = hp[(long)t0.x * C4 + c];
        acc.x += w0 * v0.x;
        acc.y += w0 * v0.y;
        acc.z += w0 * v0.z;
        acc.w += w0 * v0.w;
    }

    if (EPI == 1) {
        float4 bb = *reinterpret_cast<const float4*>(bias + c * 4);
        acc.x = fmaxf(acc.x + bb.x, 0.f);
        acc.y = fmaxf(acc.y + bb.y, 0.f);
        acc.z = fmaxf(acc.z + bb.z, 0.f);
        acc.w = fmaxf(acc.w + bb.w, 0.f);
    }
    acc.x = rnd_tf32(acc.x);
    acc.y = rnd_tf32(acc.y);
    acc.z = rnd_tf32(acc.z);
    acc.w = rnd_tf32(acc.w);

    reinterpret_cast<float4*>(agg)[(long)n * C4 + c] = acc;
}

// =========================================================
// Fused layer-3 aggregation + bias + log_softmax.
// One warp per node: lane holds ch=lane, and ch=32+lane for lane<8.
// out[n] = log_softmax(sum_e w_e * h[src_e] + b)
// =========================================================
__global__ __launch_bounds__(256) void gather40_lsm_kernel(
    const float* __restrict__ h, const float* __restrict__ b,
    float* __restrict__ out)
{
    int n = (int)(((long)blockIdx.x * blockDim.x + threadIdx.x) >> 5);
    int lane = threadIdx.x & 31;
    if (n >= N_NODES) return;

    int e   = g_off[n];
    int end = g_off[n + 1];
    float acc0 = 0.f, acc1 = 0.f;

    for (; e + 1 < end; e += 2) {
        int2 t0 = g_csr[e];
        int2 t1 = g_csr[e + 1];
        float w0 = __int_as_float(t0.y);
        float w1 = __int_as_float(t1.y);
        const float* r0 = h + (long)t0.x * OUT_CH;
        const float* r1 = h + (long)t1.x * OUT_CH;
        acc0 += w0 * r0[lane] + w1 * r1[lane];
        if (lane < 8) acc1 += w0 * r0[32 + lane] + w1 * r1[32 + lane];
    }
    if (e < end) {
        int2 t0 = g_csr[e];
        float w0 = __int_as_float(t0.y);
        const float* r0 = h + (long)t0.x * OUT_CH;
        acc0 += w0 * r0[lane];
        if (lane < 8) acc1 += w0 * r0[32 + lane];
    }

    float v0 = acc0 + b[lane];
    float v1 = (lane < 8) ? (acc1 + b[32 + lane]) : -INFINITY;

    float m = fmaxf(v0, v1);
#pragma unroll
    for (int o = 16; o > 0; o >>= 1)
        m = fmaxf(m, __shfl_xor_sync(0xFFFFFFFFu, m, o));

    float s = __expf(v0 - m) + ((lane < 8) ? __expf(v1 - m) : 0.f);
#pragma unroll
    for (int o = 16; o > 0; o >>= 1)
        s += __shfl_xor_sync(0xFFFFFFFFu, s, o);

    float lse = m + logf(s);
    float* row = out + (long)n * OUT_CH;
    row[lane] = v0 - lse;
    if (lane < 8) row[32 + lane] = v1 - lse;
}

// ---------------------------------------------------------
// launch
// ---------------------------------------------------------
extern "C" void kernel_launch(void* const* d_in, const int* in_sizes, int n_in,
                              void* d_out, int out_size)
{
    const float* x  = (const float*)d_in[0];
    const int*   ei = (const int*)d_in[1];
    const float* ew = (const float*)d_in[2];
    const float* W1 = (const float*)d_in[3];
    const float* b1 = (const float*)d_in[4];
    const float* W2 = (const float*)d_in[5];
    const float* b2 = (const float*)d_in[6];
    const float* W3 = (const float*)d_in[7];
    const float* b3 = (const float*)d_in[8];
    float* out = (float*)d_out;

    const int* src = ei;
    const int* dst = ei + N_EDGES;

    float *buf0, *buf1, *buf2, *w1p, *w2p, *w3p;
    cudaGetSymbolAddress((void**)&buf0, g_buf0);
    cudaGetSymbolAddress((void**)&buf1, g_buf1);
    cudaGetSymbolAddress((void**)&buf2, g_buf2);
    cudaGetSymbolAddress((void**)&w1p, g_w1);
    cudaGetSymbolAddress((void**)&w2p, g_w2);
    cudaGetSymbolAddress((void**)&w3p, g_w3);

    const int mtiles = (N_NODES + GBM - 1) / GBM;   // 391
    dim3 grid_wide(HID / 128, mtiles);              // 2 x 391 (BN=128)
    dim3 grid_narrow(1, mtiles);                    // 1 x 391 (BN=64, N=40)

    // weight prep + CSR build (parallel scan)
    prep_kernel<<<(HID * HID + 255) / 256, 256>>>(W1, W2, W3);
    zero_deg_kernel<<<(N_NODES + 255) / 256, 256>>>();
    hist_kernel<<<(N_EDGES + 255) / 256, 256>>>(dst);
    scan_block_kernel<<<NSB, 256>>>();
    scan_top_kernel<<<1, 256>>>();
    scan_finalize_kernel<<<NSB, 256>>>();
    fill_kernel<<<(N_EDGES + 255) / 256, 256>>>(src, dst, ew);

    // ---- layer 1 (reordered): agg_x = A_hat @ x ; h1 = relu(agg_x @ W1 + b1) ----
    gather_kernel<32, 0><<<(N_NODES * 32 + 255) / 256, 256>>>(x, nullptr, buf1);
    gemm_tf32<1, 128><<<grid_wide, 256>>>(buf1, w1p, b1, buf0, N_NODES, HID, IN_CH);

    // ---- layer 2: h2 = h1r @ W2 ; agg2 = relu(A_hat @ h2 + b2) ----
    gemm_tf32<0, 128><<<grid_wide, 256>>>(buf0, w2p, nullptr, buf2, N_NODES, HID, HID);
    gather_kernel<64, 1><<<(N_NODES * 2 * 32 + 255) / 256, 256>>>(buf2, b2, buf1);

    // ---- layer 3: h3 = agg2r @ W3 ; out = log_softmax(A_hat @ h3 + b3) ----
    gemm_tf32<0, 64><<<grid_narrow, 256>>>(buf1, w3p, nullptr, buf0, N_NODES, OUT_CH, HID);
    gather40_lsm_kernel<<<(N_NODES * 32 + 255) / 256, 256>>>(buf0, b3, out);
}